// round 2
// baseline (speedup 1.0000x reference)
#include <cuda_runtime.h>
#include <cstdint>

#define E_DIM 128
#define H_DIM 64
#define B_SZ  1024
#define T_SZ  200
#define N_ROWS (B_SZ * T_SZ)       // 204800
#define MT 128                      // rows per tile
#define N_TILES (N_ROWS / MT)       // 1600 (exact)

// smem layout (floats)
#define OFF_WHI 0                   // 256*72
#define OFF_WLO 18432               // 256*72
#define OFF_K   36864               // 128*132
#define OFF_Q   53760               // 2*128
#define OFF_QA  54016               // 2*64
#define OFF_W1  54144               // 64
#define OFF_OUT 54208               // 128
#define SMEM_FLOATS 54336
#define SMEM_BYTES (SMEM_FLOATS * 4) // 217344 B

// Scratch (device globals: no allocation allowed)
__device__ float g_Whi[256 * 64];
__device__ float g_Wlo[256 * 64];
__device__ float g_Wq [128 * 64];
__device__ float g_qA [B_SZ * 64];

__device__ __forceinline__ void tf32_split(float x, uint32_t &hi, uint32_t &lo) {
    uint32_t h;
    asm("cvt.rna.tf32.f32 %0, %1;" : "=r"(h) : "f"(x));
    float r = x - __uint_as_float(h);
    uint32_t l;
    asm("cvt.rna.tf32.f32 %0, %1;" : "=r"(l) : "f"(r));
    hi = h; lo = l;
}

__device__ __forceinline__ void mma_tf32(float c[4], const uint32_t a[4], const uint32_t b[2]) {
    asm volatile(
        "mma.sync.aligned.m16n8k8.row.col.f32.tf32.tf32.f32 "
        "{%0,%1,%2,%3}, {%4,%5,%6,%7}, {%8,%9}, {%0,%1,%2,%3};\n"
        : "+f"(c[0]), "+f"(c[1]), "+f"(c[2]), "+f"(c[3])
        : "r"(a[0]), "r"(a[1]), "r"(a[2]), "r"(a[3]),
          "r"(b[0]), "r"(b[1]));
}

// Fold W0 [512,64]: Wk = W0b - W0c (rows 0..127), Wc = W0d (rows 128..255),
// Wq = W0a + W0c. Split Wk/Wc into tf32 hi/lo.
__global__ void prep_weights(const float* __restrict__ W0) {
    int idx = blockIdx.x * blockDim.x + threadIdx.x;
    if (idx >= 128 * 64) return;
    int e = idx >> 6, h = idx & 63;
    float wa = W0[e * 64 + h];
    float wb = W0[(128 + e) * 64 + h];
    float wc = W0[(256 + e) * 64 + h];
    float wd = W0[(384 + e) * 64 + h];
    uint32_t hi, lo;
    tf32_split(wb - wc, hi, lo);
    g_Whi[idx] = __uint_as_float(hi);
    g_Wlo[idx] = __uint_as_float(lo);
    tf32_split(wd, hi, lo);
    g_Whi[128 * 64 + idx] = __uint_as_float(hi);
    g_Wlo[128 * 64 + idx] = __uint_as_float(lo);
    g_Wq[idx] = wa + wc;
}

// qA[b][h] = b0[h] + sum_e q[b][e] * Wq[e][h]   (fp32 exact)
__global__ void prep_qA(const float* __restrict__ query, const float* __restrict__ b0) {
    __shared__ float qs[128];
    int b = blockIdx.x, h = threadIdx.x;
    qs[h]      = query[b * 128 + h];
    qs[64 + h] = query[b * 128 + 64 + h];
    __syncthreads();
    float acc = b0[h];
    #pragma unroll 8
    for (int e = 0; e < 128; e++)
        acc += qs[e] * g_Wq[e * 64 + h];
    g_qA[b * 64 + h] = acc;
}

// Persistent main kernel: 1 CTA/SM, weights staged in smem once.
// Per tile: M=128 rows, N=64, K=256 (K 0..127 = k, 128..255 = q*k),
// tf32 3-term split mma, epilogue relu + dot(W1).
__global__ void __launch_bounds__(256, 1) lau_main(
    const float* __restrict__ keys, const float* __restrict__ query,
    const float* __restrict__ W1,   const float* __restrict__ b1,
    float* __restrict__ out)
{
    extern __shared__ float sm[];
    float* sWhi = sm + OFF_WHI;   // [256][72]
    float* sWlo = sm + OFF_WLO;   // [256][72]
    float* sK   = sm + OFF_K;     // [128][132]
    float* sQ   = sm + OFF_Q;     // [2][128]
    float* sQA  = sm + OFF_QA;    // [2][64]
    float* sW1  = sm + OFF_W1;    // [64]
    float* sOut = sm + OFF_OUT;   // [128]

    int tid = threadIdx.x;

    // stage folded weights (stride 72 -> conflict-free B-frag loads: bank = 8*krow + col)
    for (int i = tid; i < 256 * 64; i += 256) {
        int r = i >> 6, c = i & 63;
        sWhi[r * 72 + c] = g_Whi[i];
        sWlo[r * 72 + c] = g_Wlo[i];
    }
    if (tid < 64) sW1[tid] = W1[tid];
    float b1v = b1[0];

    int wid = tid >> 5, lane = tid & 31;
    int wm = wid >> 1, wn = wid & 1;       // 4 x 2 warp grid (M x N)
    int lq = lane >> 2, lr = lane & 3;
    int ra = wm * 32 + lq;                 // base row (mtile 0)

    for (int tile = blockIdx.x; tile < N_TILES; tile += gridDim.x) {
        int base  = tile * MT;
        int b0i   = base / T_SZ;
        int split = (b0i + 1) * T_SZ - base;   // local rows < split belong to b0i

        if (tid < 128) sOut[tid] = 0.f;

        // K tile: 128 rows x 128 floats, padded stride 132 (conflict-free A loads)
        const float4* k4 = (const float4*)(keys + (size_t)base * E_DIM);
        for (int i = tid; i < 128 * 32; i += 256) {
            int r = i >> 5, c = i & 31;
            float4 v = k4[r * 32 + c];
            *(float4*)(sK + r * 132 + c * 4) = v;
        }
        {   // q rows for b0i and b0i+1
            int r = tid >> 7, e = tid & 127;
            int bb = b0i + r;
            sQ[tid] = (bb < B_SZ) ? query[bb * E_DIM + e] : 0.f;
        }
        if (tid < 128) {
            int bb = b0i + (tid >> 6);
            sQA[tid] = (bb < B_SZ) ? g_qA[bb * 64 + (tid & 63)] : 0.f;
        }
        __syncthreads();

        float acc[2][4][4];
        #pragma unroll
        for (int mt = 0; mt < 2; mt++)
            #pragma unroll
            for (int nt = 0; nt < 4; nt++)
                #pragma unroll
                for (int j = 0; j < 4; j++) acc[mt][nt][j] = 0.f;

        const float* qp[2][2];
        #pragma unroll
        for (int mt = 0; mt < 2; mt++) {
            int r0 = ra + mt * 16;
            qp[mt][0] = sQ + ((r0     < split) ? 0 : 128);
            qp[mt][1] = sQ + ((r0 + 8 < split) ? 0 : 128);
        }

        // ---- part 1: K cols 0..127 (A = k) ----
        #pragma unroll 4
        for (int kc = 0; kc < 16; kc++) {
            int e0 = kc * 8 + lr;
            uint32_t ahi[2][4], alo[2][4];
            #pragma unroll
            for (int mt = 0; mt < 2; mt++) {
                int r0 = ra + mt * 16;
                float v0 = sK[r0 * 132 + e0];
                float v1 = sK[(r0 + 8) * 132 + e0];
                float v2 = sK[r0 * 132 + e0 + 4];
                float v3 = sK[(r0 + 8) * 132 + e0 + 4];
                tf32_split(v0, ahi[mt][0], alo[mt][0]);
                tf32_split(v1, ahi[mt][1], alo[mt][1]);
                tf32_split(v2, ahi[mt][2], alo[mt][2]);
                tf32_split(v3, ahi[mt][3], alo[mt][3]);
            }
            int kr = kc * 8 + lr;
            #pragma unroll
            for (int nt = 0; nt < 4; nt++) {
                int col = wn * 32 + nt * 8 + lq;
                uint32_t bh[2], bl[2];
                bh[0] = __float_as_uint(sWhi[kr * 72 + col]);
                bh[1] = __float_as_uint(sWhi[(kr + 4) * 72 + col]);
                bl[0] = __float_as_uint(sWlo[kr * 72 + col]);
                bl[1] = __float_as_uint(sWlo[(kr + 4) * 72 + col]);
                #pragma unroll
                for (int mt = 0; mt < 2; mt++) {
                    mma_tf32(acc[mt][nt], ahi[mt], bh);
                    mma_tf32(acc[mt][nt], ahi[mt], bl);
                    mma_tf32(acc[mt][nt], alo[mt], bh);
                }
            }
        }

        // ---- part 2: K cols 128..255 (A = q*k) ----
        #pragma unroll 4
        for (int kc = 0; kc < 16; kc++) {
            int e0 = kc * 8 + lr;
            uint32_t ahi[2][4], alo[2][4];
            #pragma unroll
            for (int mt = 0; mt < 2; mt++) {
                int r0 = ra + mt * 16;
                float v0 = sK[r0 * 132 + e0]           * qp[mt][0][e0];
                float v1 = sK[(r0 + 8) * 132 + e0]     * qp[mt][1][e0];
                float v2 = sK[r0 * 132 + e0 + 4]       * qp[mt][0][e0 + 4];
                float v3 = sK[(r0 + 8) * 132 + e0 + 4] * qp[mt][1][e0 + 4];
                tf32_split(v0, ahi[mt][0], alo[mt][0]);
                tf32_split(v1, ahi[mt][1], alo[mt][1]);
                tf32_split(v2, ahi[mt][2], alo[mt][2]);
                tf32_split(v3, ahi[mt][3], alo[mt][3]);
            }
            int kr = 128 + kc * 8 + lr;
            #pragma unroll
            for (int nt = 0; nt < 4; nt++) {
                int col = wn * 32 + nt * 8 + lq;
                uint32_t bh[2], bl[2];
                bh[0] = __float_as_uint(sWhi[kr * 72 + col]);
                bh[1] = __float_as_uint(sWhi[(kr + 4) * 72 + col]);
                bl[0] = __float_as_uint(sWlo[kr * 72 + col]);
                bl[1] = __float_as_uint(sWlo[(kr + 4) * 72 + col]);
                #pragma unroll
                for (int mt = 0; mt < 2; mt++) {
                    mma_tf32(acc[mt][nt], ahi[mt], bh);
                    mma_tf32(acc[mt][nt], ahi[mt], bl);
                    mma_tf32(acc[mt][nt], alo[mt], bh);
                }
            }
        }

        // ---- epilogue: h = relu(acc + qA), score = h . W1 ----
        #pragma unroll
        for (int mt = 0; mt < 2; mt++) {
            int r0 = ra + mt * 16;
            int r1 = r0 + 8;
            int qa0 = (r0 < split) ? 0 : 64;
            int qa1 = (r1 < split) ? 0 : 64;
            float p0 = 0.f, p1 = 0.f;
            #pragma unroll
            for (int nt = 0; nt < 4; nt++) {
                int c0 = wn * 32 + nt * 8 + 2 * lr;
                int c1 = c0 + 1;
                float h00 = acc[mt][nt][0] + sQA[qa0 + c0];
                float h01 = acc[mt][nt][1] + sQA[qa0 + c1];
                float h10 = acc[mt][nt][2] + sQA[qa1 + c0];
                float h11 = acc[mt][nt][3] + sQA[qa1 + c1];
                p0 += fmaxf(h00, 0.f) * sW1[c0] + fmaxf(h01, 0.f) * sW1[c1];
                p1 += fmaxf(h10, 0.f) * sW1[c0] + fmaxf(h11, 0.f) * sW1[c1];
            }
            p0 += __shfl_xor_sync(0xffffffffu, p0, 1);
            p0 += __shfl_xor_sync(0xffffffffu, p0, 2);
            p1 += __shfl_xor_sync(0xffffffffu, p1, 1);
            p1 += __shfl_xor_sync(0xffffffffu, p1, 2);
            if (lr == 0) {
                atomicAdd(&sOut[r0], p0);
                atomicAdd(&sOut[r1], p1);
            }
        }
        __syncthreads();
        if (tid < 128) out[base + tid] = sOut[tid] + b1v;
        __syncthreads();
    }
}

extern "C" void kernel_launch(void* const* d_in, const int* in_sizes, int n_in,
                              void* d_out, int out_size) {
    const float* query = (const float*)d_in[0];
    const float* keys  = (const float*)d_in[1];
    const float* W0    = (const float*)d_in[2];
    const float* b0    = (const float*)d_in[3];
    const float* W1    = (const float*)d_in[4];
    const float* b1    = (const float*)d_in[5];
    float* out = (float*)d_out;

    cudaFuncSetAttribute(lau_main, cudaFuncAttributeMaxDynamicSharedMemorySize, SMEM_BYTES);

    prep_weights<<<32, 256>>>(W0);
    prep_qA<<<B_SZ, 64>>>(query, b0);
    lau_main<<<148, 256, SMEM_BYTES>>>(keys, query, W1, b1, out);
}

// round 4
// speedup vs baseline: 1.6282x; 1.6282x over previous
#include <cuda_runtime.h>
#include <cstdint>

#define E_DIM 128
#define B_SZ  1024
#define T_SZ  200
#define N_ROWS (B_SZ * T_SZ)        // 204800
#define MT 128
#define N_TILES (N_ROWS / MT)       // 1600

// A/B rows padded to 264 bf16 = 528 B (16B-step rotation across 8 rows -> conflict-free ldmatrix)
#define ROW_B 528
#define OFF_AHI 0                   // 128*528 = 67584
#define OFF_ALO 67584
#define OFF_BHI 135168              // 64*528 = 33792
#define OFF_BLO 168960
#define OFF_QA  202752              // 2*64 f32
#define OFF_W1  203264              // 64 f32
#define SMEM_BYTES 203520

// device scratch (no allocation allowed)
__device__ uint32_t g_WhiP[64 * 132];   // [n=64][kpair=128 used, stride 132] packed bf16x2
__device__ uint32_t g_WloP[64 * 132];
__device__ float    g_qA[B_SZ * 64];

__device__ __forceinline__ uint32_t pk_bf16(float lo, float hi) {
    uint32_t r;
    asm("cvt.rn.bf16x2.f32 %0, %1, %2;" : "=r"(r) : "f"(hi), "f"(lo));
    return r;
}
__device__ __forceinline__ float vlo(uint32_t w) { return __uint_as_float(w << 16); }
__device__ __forceinline__ float vhi(uint32_t w) { return __uint_as_float(w & 0xffff0000u); }

__device__ __forceinline__ uint32_t smem_u32(const void* p) {
    uint32_t a;
    asm("{ .reg .u64 t; cvta.to.shared.u64 t, %1; cvt.u32.u64 %0, t; }" : "=r"(a) : "l"(p));
    return a;
}

#define LDSM4(r, addr) \
    asm volatile("ldmatrix.sync.aligned.m8n8.x4.shared.b16 {%0,%1,%2,%3}, [%4];" \
        : "=r"((r)[0]), "=r"((r)[1]), "=r"((r)[2]), "=r"((r)[3]) : "r"(addr))

__device__ __forceinline__ void mma_bf16(float* c, const uint32_t* a, uint32_t b0, uint32_t b1) {
    asm volatile("mma.sync.aligned.m16n8k16.row.col.f32.bf16.bf16.f32 "
        "{%0,%1,%2,%3}, {%4,%5,%6,%7}, {%8,%9}, {%0,%1,%2,%3};"
        : "+f"(c[0]), "+f"(c[1]), "+f"(c[2]), "+f"(c[3])
        : "r"(a[0]), "r"(a[1]), "r"(a[2]), "r"(a[3]), "r"(b0), "r"(b1));
}

// Fold W0[512,64] -> Wt[n=64][k'=256] (k'<128: W0b-W0c ; k'>=128: W0d),
// bf16 hi/lo pairs, stored [n][kpair] stride 132 (== smem ldmatrix layout).
__global__ void prep_weights(const float* __restrict__ W0) {
    int e2 = blockIdx.x;        // 0..127 -> k' pair (2*e2, 2*e2+1)
    int h  = threadIdx.x;       // 0..63
    float v0, v1;
    {
        int k = 2 * e2;
        v0 = (k < 128) ? (W0[(128 + k) * 64 + h] - W0[(256 + k) * 64 + h])
                       : W0[(384 + (k - 128)) * 64 + h];
        k = 2 * e2 + 1;
        v1 = (k < 128) ? (W0[(128 + k) * 64 + h] - W0[(256 + k) * 64 + h])
                       : W0[(384 + (k - 128)) * 64 + h];
    }
    uint32_t hiw = pk_bf16(v0, v1);
    uint32_t low = pk_bf16(v0 - vlo(hiw), v1 - vhi(hiw));
    g_WhiP[h * 132 + e2] = hiw;
    g_WloP[h * 132 + e2] = low;
}

// qA[b][h] = b0[h] + sum_e q[b][e]*(W0a[e,h]+W0c[e,h])  (fp32 exact), 4 b-rows per block
__global__ void prep_qA(const float* __restrict__ query, const float* __restrict__ W0,
                        const float* __restrict__ b0) {
    __shared__ float qs[4][128];
    int h = threadIdx.x;                 // 0..63
    int bb = blockIdx.x * 4;
    #pragma unroll
    for (int j = 0; j < 4; j++) {
        qs[j][h]      = query[(bb + j) * 128 + h];
        qs[j][64 + h] = query[(bb + j) * 128 + 64 + h];
    }
    __syncthreads();
    float bias = b0[h];
    float a0 = bias, a1 = bias, a2 = bias, a3 = bias;
    #pragma unroll 4
    for (int e = 0; e < 128; e++) {
        float wv = W0[e * 64 + h] + W0[(256 + e) * 64 + h];
        a0 += qs[0][e] * wv;
        a1 += qs[1][e] * wv;
        a2 += qs[2][e] * wv;
        a3 += qs[3][e] * wv;
    }
    g_qA[(bb + 0) * 64 + h] = a0;
    g_qA[(bb + 1) * 64 + h] = a1;
    g_qA[(bb + 2) * 64 + h] = a2;
    g_qA[(bb + 3) * 64 + h] = a3;
}

__global__ void __launch_bounds__(256, 1) lau_main(
    const float* __restrict__ keys, const float* __restrict__ query,
    const float* __restrict__ W1,   const float* __restrict__ b1,
    float* __restrict__ out)
{
    extern __shared__ __align__(1024) char sm[];
    const uint32_t smb = smem_u32(sm);
    const int tid = threadIdx.x;
    const int w = tid >> 5, lane = tid & 31;
    const int lq = lane >> 2, lr = lane & 3;

    // stage folded weights (layout-preserving: already [n][132] u32)
    for (int i = tid; i < 2112; i += 256) {
        ((uint4*)(sm + OFF_BHI))[i] = ((const uint4*)g_WhiP)[i];
        ((uint4*)(sm + OFF_BLO))[i] = ((const uint4*)g_WloP)[i];
    }
    if (tid < 64) ((float*)(sm + OFF_W1))[tid] = W1[tid];
    const float b1v = b1[0];
    __syncthreads();

    // per-thread W1 values for the epilogue columns
    float w1v[16];
    {
        const float* sW1 = (const float*)(sm + OFF_W1);
        #pragma unroll
        for (int nt = 0; nt < 8; nt++) {
            w1v[2 * nt]     = sW1[nt * 8 + 2 * lr];
            w1v[2 * nt + 1] = sW1[nt * 8 + 2 * lr + 1];
        }
    }
    float* sQA = (float*)(sm + OFF_QA);

    // ldmatrix base addresses
    const uint32_t aHi = smb + OFF_AHI + (w * 16 + (lane & 15)) * ROW_B + (lane >> 4) * 16;
    const uint32_t aLo = aHi + (OFF_ALO - OFF_AHI);
    const int bn = (lane & 7) + ((lane >> 4) & 1) * 8;
    const int bk = ((lane >> 3) & 1) * 8;
    const uint32_t bHi = smb + OFF_BHI + bn * ROW_B + bk * 2;
    const uint32_t bLo = bHi + (OFF_BLO - OFF_BHI);

    for (int tile = blockIdx.x; tile < N_TILES; tile += gridDim.x) {
        const int base = tile * MT;
        const int b0i = base / T_SZ;
        const int split = (b0i + 1) * T_SZ - base;   // rows < split -> batch b0i

        if (tid < 128) {
            int bb = b0i + (tid >> 6);
            sQA[tid] = (bb < B_SZ) ? g_qA[bb * 64 + (tid & 63)] : 0.f;
        }

        // ---- prep: keys -> bf16 hi/lo (k and q*k), swizzle-free padded layout ----
        const float4* k4 = (const float4*)(keys + (size_t)base * E_DIM);
        #pragma unroll
        for (int i = 0; i < 16; i++) {
            int idx = i * 256 + tid;          // coalesced float4 index
            int row = idx >> 5, c4 = idx & 31;
            float4 kv = __ldg(&k4[idx]);
            const float4* qp = (const float4*)(query + (size_t)(b0i + (row >= split)) * E_DIM) + c4;
            float4 qv = __ldg(qp);
            uint32_t kh0 = pk_bf16(kv.x, kv.y), kh1 = pk_bf16(kv.z, kv.w);
            uint32_t kl0 = pk_bf16(kv.x - vlo(kh0), kv.y - vhi(kh0));
            uint32_t kl1 = pk_bf16(kv.z - vlo(kh1), kv.w - vhi(kh1));
            float p0 = kv.x * qv.x, p1 = kv.y * qv.y, p2 = kv.z * qv.z, p3 = kv.w * qv.w;
            uint32_t qh0 = pk_bf16(p0, p1), qh1 = pk_bf16(p2, p3);
            uint32_t ql0 = pk_bf16(p0 - vlo(qh0), p1 - vhi(qh0));
            uint32_t ql1 = pk_bf16(p2 - vlo(qh1), p3 - vhi(qh1));
            char* pa = sm + row * ROW_B + c4 * 8;
            *(uint2*)(pa + OFF_AHI)       = make_uint2(kh0, kh1);
            *(uint2*)(pa + OFF_ALO)       = make_uint2(kl0, kl1);
            *(uint2*)(pa + OFF_AHI + 256) = make_uint2(qh0, qh1);   // k' = 128 + e
            *(uint2*)(pa + OFF_ALO + 256) = make_uint2(ql0, ql1);
        }
        __syncthreads();

        // ---- mma mainloop: M16(warp) x N64 x K256, 3-term bf16 split ----
        float acc[8][4];
        #pragma unroll
        for (int nt = 0; nt < 8; nt++)
            #pragma unroll
            for (int j = 0; j < 4; j++) acc[nt][j] = 0.f;

        #pragma unroll 4
        for (int ks = 0; ks < 16; ks++) {
            uint32_t ah[4], al[4];
            LDSM4(ah, aHi + ks * 32);
            LDSM4(al, aLo + ks * 32);
            #pragma unroll
            for (int p = 0; p < 4; p++) {
                uint32_t bh[4], bl[4];
                LDSM4(bh, bHi + p * (16 * ROW_B) + ks * 32);
                LDSM4(bl, bLo + p * (16 * ROW_B) + ks * 32);
                mma_bf16(acc[2 * p],     ah, bh[0], bh[1]);
                mma_bf16(acc[2 * p + 1], ah, bh[2], bh[3]);
                mma_bf16(acc[2 * p],     ah, bl[0], bl[1]);
                mma_bf16(acc[2 * p + 1], ah, bl[2], bl[3]);
                mma_bf16(acc[2 * p],     al, bh[0], bh[1]);
                mma_bf16(acc[2 * p + 1], al, bh[2], bh[3]);
            }
        }

        // ---- epilogue: h = relu(acc + qA), score = h . W1 + b1 ----
        const int row0 = w * 16 + lq, row1 = row0 + 8;
        const float* qa0 = sQA + ((row0 < split) ? 0 : 64);
        const float* qa1 = sQA + ((row1 < split) ? 0 : 64);
        float s0 = 0.f, s1 = 0.f;
        #pragma unroll
        for (int nt = 0; nt < 8; nt++) {
            int c0 = nt * 8 + 2 * lr;
            float h;
            h = acc[nt][0] + qa0[c0];     s0 += fmaxf(h, 0.f) * w1v[2 * nt];
            h = acc[nt][1] + qa0[c0 + 1]; s0 += fmaxf(h, 0.f) * w1v[2 * nt + 1];
            h = acc[nt][2] + qa1[c0];     s1 += fmaxf(h, 0.f) * w1v[2 * nt];
            h = acc[nt][3] + qa1[c0 + 1]; s1 += fmaxf(h, 0.f) * w1v[2 * nt + 1];
        }
        s0 += __shfl_xor_sync(0xffffffffu, s0, 1);
        s0 += __shfl_xor_sync(0xffffffffu, s0, 2);
        s1 += __shfl_xor_sync(0xffffffffu, s1, 1);
        s1 += __shfl_xor_sync(0xffffffffu, s1, 2);
        if (lr == 0) {
            out[base + row0] = s0 + b1v;
            out[base + row1] = s1 + b1v;
        }
        __syncthreads();
    }
}

extern "C" void kernel_launch(void* const* d_in, const int* in_sizes, int n_in,
                              void* d_out, int out_size) {
    const float* query = (const float*)d_in[0];
    const float* keys  = (const float*)d_in[1];
    const float* W0    = (const float*)d_in[2];
    const float* b0    = (const float*)d_in[3];
    const float* W1    = (const float*)d_in[4];
    const float* b1    = (const float*)d_in[5];
    float* out = (float*)d_out;

    cudaFuncSetAttribute(lau_main, cudaFuncAttributeMaxDynamicSharedMemorySize, SMEM_BYTES);

    prep_weights<<<128, 64>>>(W0);
    prep_qA<<<B_SZ / 4, 64>>>(query, W0, b0);
    lau_main<<<148, 256, SMEM_BYTES>>>(keys, query, W1, b1, out);
}

// round 5
// speedup vs baseline: 1.9464x; 1.1954x over previous
#include <cuda_runtime.h>
#include <cstdint>

#define E_DIM 128
#define B_SZ  1024
#define T_SZ  200

#define ROW_A 272            // 128 fp16 = 256B padded to 272B (17 granules, ldmatrix conflict-free)
#define ROW_B 272

#define OFF_A   0            // 208 * 272 = 56576
#define OFF_BH  56576        // 64 * 272  = 17408
#define OFF_BL  73984        // 17408
#define OFF_WK  91392        // 64 * 130 * 4 = 33280 (fp32, [h*130 + e])
#define OFF_WD  124672       // 33280
#define OFF_QA  157952       // 64 f32
#define OFF_W1  158208       // 64 f32
#define OFF_OUT 158464       // 208 f32
#define SMEM_BYTES 159296

__device__ float g_qA[B_SZ * 64];

__device__ __forceinline__ uint32_t pkf16(float lo, float hi) {
    uint32_t r;
    asm("cvt.rn.f16x2.f32 %0, %1, %2;" : "=r"(r) : "f"(hi), "f"(lo));
    return r;
}
__device__ __forceinline__ void upkf16(uint32_t p, float& a, float& b) {
    asm("{.reg .b16 l,h; mov.b32 {l,h}, %2; cvt.f32.f16 %0, l; cvt.f32.f16 %1, h;}"
        : "=f"(a), "=f"(b) : "r"(p));
}
__device__ __forceinline__ uint32_t smem_u32(const void* p) {
    uint32_t a;
    asm("{ .reg .u64 t; cvta.to.shared.u64 t, %1; cvt.u32.u64 %0, t; }" : "=r"(a) : "l"(p));
    return a;
}

#define LDSM4(r, addr) \
    asm volatile("ldmatrix.sync.aligned.m8n8.x4.shared.b16 {%0,%1,%2,%3}, [%4];" \
        : "=r"((r)[0]), "=r"((r)[1]), "=r"((r)[2]), "=r"((r)[3]) : "r"(addr))

__device__ __forceinline__ void mma_f16(float* c, const uint32_t* a, uint32_t b0, uint32_t b1) {
    asm volatile("mma.sync.aligned.m16n8k16.row.col.f32.f16.f16.f32 "
        "{%0,%1,%2,%3}, {%4,%5,%6,%7}, {%8,%9}, {%0,%1,%2,%3};"
        : "+f"(c[0]), "+f"(c[1]), "+f"(c[2]), "+f"(c[3])
        : "r"(a[0]), "r"(a[1]), "r"(a[2]), "r"(a[3]), "r"(b0), "r"(b1));
}

// qA[b][h] = b0[h] + sum_e q[b][e]*(W0a[e,h]+W0c[e,h])  (fp32 exact), 4 batches per block
__global__ void prep_qA(const float* __restrict__ query, const float* __restrict__ W0,
                        const float* __restrict__ b0) {
    __shared__ float qs[4][128];
    int h = threadIdx.x;
    int bb = blockIdx.x * 4;
    #pragma unroll
    for (int j = 0; j < 4; j++) {
        qs[j][h]      = query[(bb + j) * 128 + h];
        qs[j][64 + h] = query[(bb + j) * 128 + 64 + h];
    }
    __syncthreads();
    float bias = b0[h];
    float a0 = bias, a1 = bias, a2 = bias, a3 = bias;
    #pragma unroll 4
    for (int e = 0; e < 128; e++) {
        float wv = W0[e * 64 + h] + W0[(256 + e) * 64 + h];
        a0 += qs[0][e] * wv;
        a1 += qs[1][e] * wv;
        a2 += qs[2][e] * wv;
        a3 += qs[3][e] * wv;
    }
    g_qA[(bb + 0) * 64 + h] = a0;
    g_qA[(bb + 1) * 64 + h] = a1;
    g_qA[(bb + 2) * 64 + h] = a2;
    g_qA[(bb + 3) * 64 + h] = a3;
}

// Persistent: one batch per CTA iteration. h = k·W_b + qA_b, W_b = Wk + diag(q_b)·Wd.
// fp16 2-term split: C = ah·bh + ah·bl (B exact to 2^-22, A rounded to 2^-11).
__global__ void __launch_bounds__(256, 1) lau_main(
    const float* __restrict__ keys, const float* __restrict__ query,
    const float* __restrict__ W0,   const float* __restrict__ W1,
    const float* __restrict__ b1,   float* __restrict__ out)
{
    extern __shared__ __align__(1024) char sm[];
    const uint32_t smb = smem_u32(sm);
    const int tid = threadIdx.x;
    const int w = tid >> 5, lane = tid & 31;
    const int lq = lane >> 2, lr = lane & 3;

    float* sWk  = (float*)(sm + OFF_WK);
    float* sWd  = (float*)(sm + OFF_WD);
    float* sQA  = (float*)(sm + OFF_QA);
    float* sW1  = (float*)(sm + OFF_W1);
    float* sOut = (float*)(sm + OFF_OUT);

    // stage folded fp32 weights once: Wk = W0b - W0c, Wd = W0d, layout [h*130 + e]
    for (int idx = tid; idx < 8192; idx += 256) {
        int h = idx & 63, e = idx >> 6;
        float wb = W0[(128 + e) * 64 + h];
        float wc = W0[(256 + e) * 64 + h];
        float wd = W0[(384 + e) * 64 + h];
        sWk[h * 130 + e] = wb - wc;
        sWd[h * 130 + e] = wd;
    }
    if (tid < 64) sW1[tid] = W1[tid];
    const float b1v = b1[0];
    __syncthreads();

    const int c0 = w * 8 + 2 * lr;                 // this thread's two h-columns
    const float w1a = sW1[c0], w1b = sW1[c0 + 1];

    const int wbh = tid & 63, wbe = (tid >> 6) * 32;   // W_b build mapping

    // ldmatrix bases
    const uint32_t aB  = smb + OFF_A  + (lane & 15) * ROW_A + (lane >> 4) * 16;
    const uint32_t bBH = smb + OFF_BH + (w * 8 + (lane & 7)) * ROW_B + ((lane >> 3) & 3) * 16;
    const uint32_t bBL = bBH + (OFF_BL - OFF_BH);

    for (int b = blockIdx.x; b < B_SZ; b += gridDim.x) {
        // ---- phase 1: A prep, W_b build, qA, zero sOut ----
        const float4* k4 = (const float4*)(keys + (size_t)b * T_SZ * E_DIM);
        #pragma unroll
        for (int i = 0; i < 25; i++) {
            int idx = i * 256 + tid;          // 6400 float4 = 200x128 floats
            int row = idx >> 5, cc = idx & 31;
            float4 kv = __ldg(&k4[idx]);
            uint32_t u0 = pkf16(kv.x, kv.y);
            uint32_t u1 = pkf16(kv.z, kv.w);
            *(uint2*)(sm + OFF_A + row * ROW_A + cc * 8) = make_uint2(u0, u1);
        }
        {
            const float2* q2 = (const float2*)(query + (size_t)b * E_DIM);
            #pragma unroll 4
            for (int i = 0; i < 16; i++) {
                int e = wbe + 2 * i;
                float2 qv = __ldg(&q2[e >> 1]);
                float v0 = fmaf(qv.x, sWd[wbh * 130 + e],     sWk[wbh * 130 + e]);
                float v1 = fmaf(qv.y, sWd[wbh * 130 + e + 1], sWk[wbh * 130 + e + 1]);
                uint32_t hp = pkf16(v0, v1);
                float f0, f1;
                upkf16(hp, f0, f1);
                uint32_t lp = pkf16(v0 - f0, v1 - f1);
                *(uint32_t*)(sm + OFF_BH + wbh * ROW_B + e * 2) = hp;
                *(uint32_t*)(sm + OFF_BL + wbh * ROW_B + e * 2) = lp;
            }
        }
        if (tid < 64)  sQA[tid] = g_qA[b * 64 + tid];
        if (tid < 208) sOut[tid] = 0.f;
        __syncthreads();

        // ---- phase 2: B preload (regs), mma, epilogue ----
        uint32_t bfh[8][2], bfl[8][2];
        #pragma unroll
        for (int k2 = 0; k2 < 4; k2++) {
            uint32_t t[4];
            LDSM4(t, bBH + k2 * 64);
            bfh[2*k2][0] = t[0]; bfh[2*k2][1] = t[1];
            bfh[2*k2+1][0] = t[2]; bfh[2*k2+1][1] = t[3];
            LDSM4(t, bBL + k2 * 64);
            bfl[2*k2][0] = t[0]; bfl[2*k2][1] = t[1];
            bfl[2*k2+1][0] = t[2]; bfl[2*k2+1][1] = t[3];
        }

        float acc[13][4];
        #pragma unroll
        for (int mt = 0; mt < 13; mt++)
            #pragma unroll
            for (int j = 0; j < 4; j++) acc[mt][j] = 0.f;

        #pragma unroll
        for (int mt = 0; mt < 13; mt++) {
            #pragma unroll
            for (int ks = 0; ks < 8; ks++) {
                uint32_t a[4];
                LDSM4(a, aB + mt * (16 * ROW_A) + ks * 32);
                mma_f16(acc[mt], a, bfh[ks][0], bfh[ks][1]);
                mma_f16(acc[mt], a, bfl[ks][0], bfl[ks][1]);
            }
        }

        // epilogue: h = relu(acc + qA), partial dot over this warp's 2 cols, reduce over lr
        const float qa0 = sQA[c0], qa1 = sQA[c0 + 1];
        #pragma unroll
        for (int mt = 0; mt < 13; mt++) {
            float p0 = fmaxf(acc[mt][0] + qa0, 0.f) * w1a + fmaxf(acc[mt][1] + qa1, 0.f) * w1b;
            float p1 = fmaxf(acc[mt][2] + qa0, 0.f) * w1a + fmaxf(acc[mt][3] + qa1, 0.f) * w1b;
            p0 += __shfl_xor_sync(0xffffffffu, p0, 1);
            p0 += __shfl_xor_sync(0xffffffffu, p0, 2);
            p1 += __shfl_xor_sync(0xffffffffu, p1, 1);
            p1 += __shfl_xor_sync(0xffffffffu, p1, 2);
            if (lr == 0) {
                atomicAdd(&sOut[mt * 16 + lq], p0);
                atomicAdd(&sOut[mt * 16 + lq + 8], p1);
            }
        }
        __syncthreads();

        // ---- phase 3: writeout ----
        if (tid < T_SZ) out[(size_t)b * T_SZ + tid] = sOut[tid] + b1v;
        __syncthreads();
    }
}

extern "C" void kernel_launch(void* const* d_in, const int* in_sizes, int n_in,
                              void* d_out, int out_size) {
    const float* query = (const float*)d_in[0];
    const float* keys  = (const float*)d_in[1];
    const float* W0    = (const float*)d_in[2];
    const float* b0    = (const float*)d_in[3];
    const float* W1    = (const float*)d_in[4];
    const float* b1    = (const float*)d_in[5];
    float* out = (float*)d_out;

    cudaFuncSetAttribute(lau_main, cudaFuncAttributeMaxDynamicSharedMemorySize, SMEM_BYTES);

    prep_qA<<<B_SZ / 4, 64>>>(query, W0, b0);
    lau_main<<<148, 256, SMEM_BYTES>>>(keys, query, W0, W1, b1, out);
}

// round 7
// speedup vs baseline: 2.1161x; 1.0872x over previous
#include <cuda_runtime.h>
#include <cstdint>

#define E_DIM 128
#define B_SZ  1024
#define T_SZ  200
#define GRID  148
#define NTHR  512

#define ROW_A 272            // 128 fp16 padded to 272B (17 granules, ldmatrix conflict-free)
#define ROW_B 272
#define ROW_W 130

#define OFF_A    0           // 208*272 = 56576
#define OFF_BH   56576       // 64*272  = 17408
#define OFF_BL   73984       // 17408
#define OFF_WK   91392       // 64*130*4 = 33280 fp32 [h*130+e]
#define OFF_WD   124672      // 33280
#define OFF_STG  157952      // 2 x 25600 fp32 staging (50 rows each)
#define STG_SZ   25600
#define OFF_QA   209152      // 7*64 f32 (qA for this CTA's batches)
#define OFF_RED  210944      // 8*64 f32 reduce scratch
#define OFF_W1   212992      // 64 f32
#define OFF_OUT  213248      // 208 f32
#define SMEM_BYTES 214080

__device__ __forceinline__ uint32_t pkf16(float lo, float hi) {
    uint32_t r;
    asm("cvt.rn.f16x2.f32 %0, %1, %2;" : "=r"(r) : "f"(hi), "f"(lo));
    return r;
}
__device__ __forceinline__ void upkf16(uint32_t p, float& a, float& b) {
    asm("{.reg .b16 l,h; mov.b32 {l,h}, %2; cvt.f32.f16 %0, l; cvt.f32.f16 %1, h;}"
        : "=f"(a), "=f"(b) : "r"(p));
}
__device__ __forceinline__ uint32_t smem_u32(const void* p) {
    uint32_t a;
    asm("{ .reg .u64 t; cvta.to.shared.u64 t, %1; cvt.u32.u64 %0, t; }" : "=r"(a) : "l"(p));
    return a;
}
__device__ __forceinline__ void cp16(uint32_t dst, const float4* src) {
    asm volatile("cp.async.cg.shared.global [%0], [%1], 16;"
                 :: "r"(dst), "l"(__cvta_generic_to_global(src)) : "memory");
}
#define CP_COMMIT() asm volatile("cp.async.commit_group;" ::: "memory")
#define CP_WAIT0()  asm volatile("cp.async.wait_group 0;" ::: "memory")

#define LDSM4(r, addr) \
    asm volatile("ldmatrix.sync.aligned.m8n8.x4.shared.b16 {%0,%1,%2,%3}, [%4];" \
        : "=r"((r)[0]), "=r"((r)[1]), "=r"((r)[2]), "=r"((r)[3]) : "r"(addr))

__device__ __forceinline__ void mma_f16(float* c, const uint32_t* a, uint32_t b0, uint32_t b1) {
    asm volatile("mma.sync.aligned.m16n8k16.row.col.f32.f16.f16.f32 "
        "{%0,%1,%2,%3}, {%4,%5,%6,%7}, {%8,%9}, {%0,%1,%2,%3};"
        : "+f"(c[0]), "+f"(c[1]), "+f"(c[2]), "+f"(c[3])
        : "r"(a[0]), "r"(a[1]), "r"(a[2]), "r"(a[3]), "r"(b0), "r"(b1));
}

__device__ __forceinline__ void issue_chunk(uint32_t stg, const float* keys, int b, int c, int tid) {
    const float4* src = (const float4*)(keys + ((size_t)b * T_SZ + c * 50) * E_DIM);
    #pragma unroll
    for (int i = 0; i < 4; i++) {
        int idx = i * NTHR + tid;
        if (idx < 1600) cp16(stg + idx * 16, src + idx);
    }
    CP_COMMIT();
}

__global__ void __launch_bounds__(NTHR, 1) lau_main(
    const float* __restrict__ keys, const float* __restrict__ query,
    const float* __restrict__ W0,   const float* __restrict__ b0,
    const float* __restrict__ W1,   const float* __restrict__ b1,
    float* __restrict__ out)
{
    extern __shared__ __align__(1024) char sm[];
    const uint32_t smb = smem_u32(sm);
    const int tid = threadIdx.x;
    const int w = tid >> 5, lane = tid & 31;
    const int wn = w & 7, wg = w >> 3;
    const int lq = lane >> 2, lr = lane & 3;

    float* sWk  = (float*)(sm + OFF_WK);
    float* sWd  = (float*)(sm + OFF_WD);
    float* sQA  = (float*)(sm + OFF_QA);
    float* sRed = (float*)(sm + OFF_RED);
    float* sW1  = (float*)(sm + OFF_W1);
    float* sOut = (float*)(sm + OFF_OUT);
    float* sWq  = (float*)(sm + OFF_STG);   // temp in staging area (prologue only)

    // ---- prologue: fold W0; Wq in staging; zero A tail rows ----
    for (int idx = tid; idx < 8192; idx += NTHR) {
        int h = idx & 63, e = idx >> 6;
        float wa = W0[e * 64 + h];
        float wb = W0[(128 + e) * 64 + h];
        float wc = W0[(256 + e) * 64 + h];
        float wd = W0[(384 + e) * 64 + h];
        sWk[h * ROW_W + e] = wb - wc;
        sWd[h * ROW_W + e] = wd;
        sWq[h * ROW_W + e] = wa + wc;
    }
    for (int i = tid; i < 544; i += NTHR)
        ((uint32_t*)(sm + OFF_A + 200 * ROW_A))[i] = 0;
    if (tid < 64) sW1[tid] = W1[tid];
    const float b1v = __ldg(b1);
    __syncthreads();

    // ---- prologue: qA for this CTA's batches ----
    const int h6 = tid & 63, grp = tid >> 6;
    {
        int jj = 0;
        for (int b = blockIdx.x; b < B_SZ; b += GRID, jj++) {
            float p = 0.f;
            #pragma unroll 4
            for (int i = 0; i < 16; i++) {
                int e = grp * 16 + i;
                p += __ldg(&query[(size_t)b * E_DIM + e]) * sWq[h6 * ROW_W + e];
            }
            sRed[grp * 64 + h6] = p;
            __syncthreads();
            if (tid < 64) {
                float s = __ldg(&b0[tid]);
                #pragma unroll
                for (int g = 0; g < 8; g++) s += sRed[g * 64 + tid];
                sQA[jj * 64 + tid] = s;
            }
            __syncthreads();
        }
    }

    // epilogue constants
    const int c0 = wn * 8 + 2 * lr;
    const float w1a = sW1[c0], w1b = sW1[c0 + 1];

    // ldmatrix bases
    const uint32_t aB  = smb + OFF_A  + (lane & 15) * ROW_A + (lane >> 4) * 16;
    const uint32_t bBH = smb + OFF_BH + (wn * 8 + (lane & 7)) * ROW_B + ((lane >> 3) & 3) * 16;
    const uint32_t bBL = bBH + (OFF_BL - OFF_BH);

    // kick first chunk
    issue_chunk(smb + OFF_STG, keys, blockIdx.x, 0, tid);

    int j = 0;
    for (int b = blockIdx.x; b < B_SZ; b += GRID, j++) {
        // ---- 4 pipelined 50-row chunks ----
        #pragma unroll 1
        for (int c = 0; c < 4; c++) {
            CP_WAIT0();
            __syncthreads();
            // issue next chunk (ping-pong buffer)
            int nc = c + 1, nb = b;
            if (nc == 4) { nc = 0; nb = b + GRID; }
            if (nb < B_SZ)
                issue_chunk(smb + OFF_STG + ((c + 1) & 1) * STG_SZ, keys, nb, nc, tid);
            // convert current chunk fp32 -> fp16 A
            const float4* s4 = (const float4*)(sm + OFF_STG + (c & 1) * STG_SZ);
            #pragma unroll
            for (int i = 0; i < 4; i++) {
                int idx = i * NTHR + tid;
                if (idx < 1600) {
                    float4 kv = s4[idx];
                    int row = c * 50 + (idx >> 5), cc = idx & 31;
                    uint32_t u0 = pkf16(kv.x, kv.y);
                    uint32_t u1 = pkf16(kv.z, kv.w);
                    *(uint2*)(sm + OFF_A + row * ROW_A + cc * 8) = make_uint2(u0, u1);
                }
            }
            if (c == 0) {
                // W_b = Wk + diag(q_b) Wd, fp16 hi/lo split
                const float* qb = query + (size_t)b * E_DIM;
                #pragma unroll 4
                for (int i = 0; i < 8; i++) {
                    int e = grp * 16 + 2 * i;
                    float q0 = __ldg(&qb[e]), q1 = __ldg(&qb[e + 1]);
                    float v0 = fmaf(q0, sWd[h6 * ROW_W + e],     sWk[h6 * ROW_W + e]);
                    float v1 = fmaf(q1, sWd[h6 * ROW_W + e + 1], sWk[h6 * ROW_W + e + 1]);
                    uint32_t hp = pkf16(v0, v1);
                    float f0, f1;
                    upkf16(hp, f0, f1);
                    uint32_t lp = pkf16(v0 - f0, v1 - f1);
                    *(uint32_t*)(sm + OFF_BH + h6 * ROW_B + e * 2) = hp;
                    *(uint32_t*)(sm + OFF_BL + h6 * ROW_B + e * 2) = lp;
                }
                if (tid < 208) sOut[tid] = 0.f;
            }
        }
        __syncthreads();   // A + B complete

        // ---- B fragments to registers ----
        uint32_t bfh[8][2], bfl[8][2];
        #pragma unroll
        for (int k2 = 0; k2 < 4; k2++) {
            uint32_t t[4];
            LDSM4(t, bBH + k2 * 64);
            bfh[2*k2][0] = t[0]; bfh[2*k2][1] = t[1];
            bfh[2*k2+1][0] = t[2]; bfh[2*k2+1][1] = t[3];
            LDSM4(t, bBL + k2 * 64);
            bfl[2*k2][0] = t[0]; bfl[2*k2][1] = t[1];
            bfl[2*k2+1][0] = t[2]; bfl[2*k2+1][1] = t[3];
        }

        // ---- mma: this warp-group's m-tiles ----
        const int nmt = 7 - wg;            // wg0: tiles 0-6, wg1: tiles 7-12
        float acc[7][4];
        #pragma unroll
        for (int mt = 0; mt < 7; mt++)
            #pragma unroll
            for (int t = 0; t < 4; t++) acc[mt][t] = 0.f;

        #pragma unroll
        for (int mt = 0; mt < 7; mt++) {
            if (mt < nmt) {
                int gmt = wg * 7 + mt;
                #pragma unroll
                for (int ks = 0; ks < 8; ks++) {
                    uint32_t a[4];
                    LDSM4(a, aB + gmt * (16 * ROW_A) + ks * 32);
                    mma_f16(acc[mt], a, bfh[ks][0], bfh[ks][1]);
                    mma_f16(acc[mt], a, bfl[ks][0], bfl[ks][1]);
                }
            }
        }

        // ---- epilogue ----
        const float qa0 = sQA[j * 64 + c0], qa1 = sQA[j * 64 + c0 + 1];
        #pragma unroll
        for (int mt = 0; mt < 7; mt++) {
            if (mt < nmt) {
                int gmt = wg * 7 + mt;
                float p0 = fmaxf(acc[mt][0] + qa0, 0.f) * w1a + fmaxf(acc[mt][1] + qa1, 0.f) * w1b;
                float p1 = fmaxf(acc[mt][2] + qa0, 0.f) * w1a + fmaxf(acc[mt][3] + qa1, 0.f) * w1b;
                p0 += __shfl_xor_sync(0xffffffffu, p0, 1);
                p0 += __shfl_xor_sync(0xffffffffu, p0, 2);
                p1 += __shfl_xor_sync(0xffffffffu, p1, 1);
                p1 += __shfl_xor_sync(0xffffffffu, p1, 2);
                if (lr == 0) {
                    atomicAdd(&sOut[gmt * 16 + lq], p0);
                    atomicAdd(&sOut[gmt * 16 + lq + 8], p1);
                }
            }
        }
        __syncthreads();
        if (tid < T_SZ) out[(size_t)b * T_SZ + tid] = sOut[tid] + b1v;
        // next iteration's CP_WAIT0 + __syncthreads covers remaining hazards
    }
}

extern "C" void kernel_launch(void* const* d_in, const int* in_sizes, int n_in,
                              void* d_out, int out_size) {
    const float* query = (const float*)d_in[0];
    const float* keys  = (const float*)d_in[1];
    const float* W0    = (const float*)d_in[2];
    const float* b0    = (const float*)d_in[3];
    const float* W1    = (const float*)d_in[4];
    const float* b1    = (const float*)d_in[5];
    float* out = (float*)d_out;

    cudaFuncSetAttribute(lau_main, cudaFuncAttributeMaxDynamicSharedMemorySize, SMEM_BYTES);
    lau_main<<<GRID, NTHR, SMEM_BYTES>>>(keys, query, W0, b0, W1, b1, out);
}

// round 8
// speedup vs baseline: 3.0843x; 1.4575x over previous
#include <cuda_runtime.h>
#include <cstdint>

#define E_DIM 128
#define B_SZ  1024
#define T_SZ  200
#define GRID  148
#define NTHR  512

#define ROW_A 272            // 128 fp16 padded to 272B (ldmatrix conflict-free)
#define ROW_B 272

#define OFF_A    0           // 208*272 = 56576
#define OFF_BH   56576       // 64*272  = 17408
#define OFF_STG  73984       // 2 x 51200 fp32 staging (100 rows each)
#define STG_SZ   51200
#define OFF_QA   176384      // 7*64 f32
#define OFF_RED  178176      // 8*64 f32
#define OFF_W1   180224      // 64 f32
#define OFF_OUT  180480      // 208 f32
#define SMEM_BYTES 181312

__device__ __forceinline__ uint32_t pkf16(float lo, float hi) {
    uint32_t r;
    asm("cvt.rn.f16x2.f32 %0, %1, %2;" : "=r"(r) : "f"(hi), "f"(lo));
    return r;
}
__device__ __forceinline__ uint32_t smem_u32(const void* p) {
    uint32_t a;
    asm("{ .reg .u64 t; cvta.to.shared.u64 t, %1; cvt.u32.u64 %0, t; }" : "=r"(a) : "l"(p));
    return a;
}
__device__ __forceinline__ void cp16(uint32_t dst, const float4* src) {
    asm volatile("cp.async.cg.shared.global [%0], [%1], 16;"
                 :: "r"(dst), "l"(__cvta_generic_to_global(src)) : "memory");
}
#define CP_COMMIT() asm volatile("cp.async.commit_group;" ::: "memory")
#define CP_WAIT(n)  asm volatile("cp.async.wait_group %0;" :: "n"(n) : "memory")

#define LDSM4(r, addr) \
    asm volatile("ldmatrix.sync.aligned.m8n8.x4.shared.b16 {%0,%1,%2,%3}, [%4];" \
        : "=r"((r)[0]), "=r"((r)[1]), "=r"((r)[2]), "=r"((r)[3]) : "r"(addr))

__device__ __forceinline__ void mma_f16(float* c, const uint32_t* a, uint32_t b0, uint32_t b1) {
    asm volatile("mma.sync.aligned.m16n8k16.row.col.f32.f16.f16.f32 "
        "{%0,%1,%2,%3}, {%4,%5,%6,%7}, {%8,%9}, {%0,%1,%2,%3};"
        : "+f"(c[0]), "+f"(c[1]), "+f"(c[2]), "+f"(c[3])
        : "r"(a[0]), "r"(a[1]), "r"(a[2]), "r"(a[3]), "r"(b0), "r"(b1));
}

// stage 100 key rows (3200 float4) into one staging buffer
__device__ __forceinline__ void issue_chunk(uint32_t stg, const float* keys, int b, int c, int tid) {
    const float4* src = (const float4*)(keys + ((size_t)b * T_SZ + c * 100) * E_DIM);
    #pragma unroll
    for (int i = 0; i < 7; i++) {
        int idx = i * NTHR + tid;
        if (idx < 3200) cp16(stg + idx * 16, src + idx);
    }
    CP_COMMIT();
}

__global__ void __launch_bounds__(NTHR, 1) lau_main(
    const float* __restrict__ keys, const float* __restrict__ query,
    const float* __restrict__ W0,   const float* __restrict__ b0,
    const float* __restrict__ W1,   const float* __restrict__ b1,
    float* __restrict__ out)
{
    extern __shared__ __align__(1024) char sm[];
    const uint32_t smb = smem_u32(sm);
    const int tid = threadIdx.x;
    const int w = tid >> 5, lane = tid & 31;
    const int wn = w & 7, wg = w >> 3;
    const int lq = lane >> 2, lr = lane & 3;

    float* sQA  = (float*)(sm + OFF_QA);
    float* sRed = (float*)(sm + OFF_RED);
    float* sW1  = (float*)(sm + OFF_W1);
    float* sOut = (float*)(sm + OFF_OUT);

    // ---- prologue: fold W0 slices into registers ----
    const int h6 = tid & 63, eb = (tid >> 6) * 16;
    float rWk[16], rWd[16], rWq[16];
    #pragma unroll
    for (int i = 0; i < 16; i++) {
        int e = eb + i;
        float wa = __ldg(&W0[e * 64 + h6]);
        float wb = __ldg(&W0[(128 + e) * 64 + h6]);
        float wc = __ldg(&W0[(256 + e) * 64 + h6]);
        float wd = __ldg(&W0[(384 + e) * 64 + h6]);
        rWk[i] = wb - wc;
        rWd[i] = wd;
        rWq[i] = wa + wc;
    }
    for (int i = tid; i < 544; i += NTHR)
        ((uint32_t*)(sm + OFF_A + 200 * ROW_A))[i] = 0;   // zero A tail rows 200-207
    if (tid < 64) sW1[tid] = W1[tid];
    const float b1v = __ldg(b1);

    // kick both chunks of first batch
    issue_chunk(smb + OFF_STG,          keys, blockIdx.x, 0, tid);
    issue_chunk(smb + OFF_STG + STG_SZ, keys, blockIdx.x, 1, tid);
    __syncthreads();

    // ---- prologue: qA for this CTA's batches (fp32 exact) ----
    {
        int jj = 0;
        for (int b = blockIdx.x; b < B_SZ; b += GRID, jj++) {
            const float* qb = query + (size_t)b * E_DIM;
            float p = 0.f;
            #pragma unroll
            for (int i = 0; i < 16; i++)
                p += __ldg(&qb[eb + i]) * rWq[i];
            sRed[(tid >> 6) * 64 + h6] = p;
            __syncthreads();
            if (tid < 64) {
                float s = __ldg(&b0[tid]);
                #pragma unroll
                for (int g = 0; g < 8; g++) s += sRed[g * 64 + tid];
                sQA[jj * 64 + tid] = s;
            }
            __syncthreads();
        }
    }

    const int c0 = wn * 8 + 2 * lr;
    const float w1a = sW1[c0], w1b = sW1[c0 + 1];

    const uint32_t aB  = smb + OFF_A  + (lane & 15) * ROW_A + (lane >> 4) * 16;
    const uint32_t bBH = smb + OFF_BH + (wn * 8 + (lane & 7)) * ROW_B + ((lane >> 3) & 3) * 16;

    int j = 0;
    for (int b = blockIdx.x; b < B_SZ; b += GRID, j++) {
        const int nb = b + GRID;

        // ---- chunk 0 ready: convert rows 0-99, build W_b, zero sOut ----
        CP_WAIT(1);
        __syncthreads();
        {
            const float4* s4 = (const float4*)(sm + OFF_STG);
            #pragma unroll
            for (int i = 0; i < 7; i++) {
                int idx = i * NTHR + tid;
                if (idx < 3200) {
                    float4 kv = s4[idx];
                    int row = idx >> 5, cc = idx & 31;
                    *(uint2*)(sm + OFF_A + row * ROW_A + cc * 8) =
                        make_uint2(pkf16(kv.x, kv.y), pkf16(kv.z, kv.w));
                }
            }
            // W_b = Wk + diag(q_b)·Wd, fp16 (single-rounded)
            const float* qb = query + (size_t)b * E_DIM;
            #pragma unroll
            for (int i = 0; i < 8; i++) {
                int e = eb + 2 * i;
                float v0 = fmaf(__ldg(&qb[e]),     rWd[2 * i],     rWk[2 * i]);
                float v1 = fmaf(__ldg(&qb[e + 1]), rWd[2 * i + 1], rWk[2 * i + 1]);
                *(uint32_t*)(sm + OFF_BH + h6 * ROW_B + e * 2) = pkf16(v0, v1);
            }
            if (tid < 208) sOut[tid] = 0.f;
        }

        // ---- chunk 1 ready: refill buf0 for next batch, convert rows 100-199 ----
        CP_WAIT(0);
        __syncthreads();
        if (nb < B_SZ) issue_chunk(smb + OFF_STG, keys, nb, 0, tid);
        {
            const float4* s4 = (const float4*)(sm + OFF_STG + STG_SZ);
            #pragma unroll
            for (int i = 0; i < 7; i++) {
                int idx = i * NTHR + tid;
                if (idx < 3200) {
                    float4 kv = s4[idx];
                    int row = 100 + (idx >> 5), cc = idx & 31;
                    *(uint2*)(sm + OFF_A + row * ROW_A + cc * 8) =
                        make_uint2(pkf16(kv.x, kv.y), pkf16(kv.z, kv.w));
                }
            }
        }
        __syncthreads();                       // A + B complete, buf1 reads done
        if (nb < B_SZ) issue_chunk(smb + OFF_STG + STG_SZ, keys, nb, 1, tid);

        // ---- B fragments ----
        uint32_t bfh[8][2];
        #pragma unroll
        for (int k2 = 0; k2 < 4; k2++) {
            uint32_t t[4];
            LDSM4(t, bBH + k2 * 64);
            bfh[2 * k2][0] = t[0];     bfh[2 * k2][1] = t[1];
            bfh[2 * k2 + 1][0] = t[2]; bfh[2 * k2 + 1][1] = t[3];
        }

        // ---- mma: wg0 tiles 0-6, wg1 tiles 7-12 ----
        const int nmt = 7 - wg;
        float acc[7][4];
        #pragma unroll
        for (int mt = 0; mt < 7; mt++)
            #pragma unroll
            for (int t = 0; t < 4; t++) acc[mt][t] = 0.f;

        #pragma unroll
        for (int mt = 0; mt < 7; mt++) {
            if (mt < nmt) {
                int gmt = wg * 7 + mt;
                #pragma unroll
                for (int ks = 0; ks < 8; ks++) {
                    uint32_t a[4];
                    LDSM4(a, aB + gmt * (16 * ROW_A) + ks * 32);
                    mma_f16(acc[mt], a, bfh[ks][0], bfh[ks][1]);
                }
            }
        }

        // ---- epilogue ----
        const float qa0 = sQA[j * 64 + c0], qa1 = sQA[j * 64 + c0 + 1];
        #pragma unroll
        for (int mt = 0; mt < 7; mt++) {
            if (mt < nmt) {
                int gmt = wg * 7 + mt;
                float p0 = fmaxf(acc[mt][0] + qa0, 0.f) * w1a + fmaxf(acc[mt][1] + qa1, 0.f) * w1b;
                float p1 = fmaxf(acc[mt][2] + qa0, 0.f) * w1a + fmaxf(acc[mt][3] + qa1, 0.f) * w1b;
                p0 += __shfl_xor_sync(0xffffffffu, p0, 1);
                p0 += __shfl_xor_sync(0xffffffffu, p0, 2);
                p1 += __shfl_xor_sync(0xffffffffu, p1, 1);
                p1 += __shfl_xor_sync(0xffffffffu, p1, 2);
                if (lr == 0) {
                    atomicAdd(&sOut[gmt * 16 + lq], p0);
                    atomicAdd(&sOut[gmt * 16 + lq + 8], p1);
                }
            }
        }
        __syncthreads();
        if (tid < T_SZ) out[(size_t)b * T_SZ + tid] = sOut[tid] + b1v;
        // next iteration's CP_WAIT(1)+sync orders sOut/A/B reuse
    }
}

extern "C" void kernel_launch(void* const* d_in, const int* in_sizes, int n_in,
                              void* d_out, int out_size) {
    const float* query = (const float*)d_in[0];
    const float* keys  = (const float*)d_in[1];
    const float* W0    = (const float*)d_in[2];
    const float* b0    = (const float*)d_in[3];
    const float* W1    = (const float*)d_in[4];
    const float* b1    = (const float*)d_in[5];
    float* out = (float*)d_out;

    cudaFuncSetAttribute(lau_main, cudaFuncAttributeMaxDynamicSharedMemorySize, SMEM_BYTES);
    lau_main<<<GRID, NTHR, SMEM_BYTES>>>(keys, query, W0, b0, W1, b1, out);
}

// round 9
// speedup vs baseline: 4.1766x; 1.3542x over previous
#include <cuda_runtime.h>
#include <cstdint>

#define E_DIM 128
#define B_SZ  1024
#define T_SZ  200
#define GRID  148
#define NTHR  512

#define ROW_A 272            // 128 fp16 padded to 272B (ldmatrix conflict-free)
#define ROW_B 272

#define OFF_A    0           // 208*272 = 56576
#define OFF_BH   56576       // 64*272  = 17408
#define OFF_STG  73984       // 2 x 51200 fp32 staging (100 rows each)
#define STG_SZ   51200
#define OFF_QA   176384      // 7*64 f32 = 1792
#define OFF_RED  178176      // 512 f32 = 2048 (qA reduce + epilogue partials)
#define OFF_W1   180224      // 64 f32
#define SMEM_BYTES 180736

__device__ __forceinline__ uint32_t pkf16(float lo, float hi) {
    uint32_t r;
    asm("cvt.rn.f16x2.f32 %0, %1, %2;" : "=r"(r) : "f"(hi), "f"(lo));
    return r;
}
__device__ __forceinline__ uint32_t smem_u32(const void* p) {
    uint32_t a;
    asm("{ .reg .u64 t; cvta.to.shared.u64 t, %1; cvt.u32.u64 %0, t; }" : "=r"(a) : "l"(p));
    return a;
}
__device__ __forceinline__ void cp16(uint32_t dst, const float4* src) {
    asm volatile("cp.async.cg.shared.global [%0], [%1], 16;"
                 :: "r"(dst), "l"(__cvta_generic_to_global(src)) : "memory");
}
#define CP_COMMIT() asm volatile("cp.async.commit_group;" ::: "memory")
#define CP_WAIT(n)  asm volatile("cp.async.wait_group %0;" :: "n"(n) : "memory")

#define LDSM4(r, addr) \
    asm volatile("ldmatrix.sync.aligned.m8n8.x4.shared.b16 {%0,%1,%2,%3}, [%4];" \
        : "=r"((r)[0]), "=r"((r)[1]), "=r"((r)[2]), "=r"((r)[3]) : "r"(addr))

__device__ __forceinline__ void mma_f16(float* c, const uint32_t* a, uint32_t b0, uint32_t b1) {
    asm volatile("mma.sync.aligned.m16n8k16.row.col.f32.f16.f16.f32 "
        "{%0,%1,%2,%3}, {%4,%5,%6,%7}, {%8,%9}, {%0,%1,%2,%3};"
        : "+f"(c[0]), "+f"(c[1]), "+f"(c[2]), "+f"(c[3])
        : "r"(a[0]), "r"(a[1]), "r"(a[2]), "r"(a[3]), "r"(b0), "r"(b1));
}

// stage 100 key rows (3200 float4) into one staging buffer
__device__ __forceinline__ void issue_chunk(uint32_t stg, const float* keys, int b, int c, int tid) {
    const float4* src = (const float4*)(keys + ((size_t)b * T_SZ + c * 100) * E_DIM);
    #pragma unroll
    for (int i = 0; i < 7; i++) {
        int idx = i * NTHR + tid;
        if (idx < 3200) cp16(stg + idx * 16, src + idx);
    }
    CP_COMMIT();
}

__global__ void __launch_bounds__(NTHR, 1) lau_main(
    const float* __restrict__ keys, const float* __restrict__ query,
    const float* __restrict__ W0,   const float* __restrict__ b0,
    const float* __restrict__ W1,   const float* __restrict__ b1,
    float* __restrict__ out)
{
    extern __shared__ __align__(1024) char sm[];
    const uint32_t smb = smem_u32(sm);
    const int tid = threadIdx.x;
    const int w = tid >> 5, lane = tid & 31;
    const int mg = w >> 1, ng = w & 1;        // 8 m-groups x 2 n-groups
    const int lq = lane >> 2, lr = lane & 3;
    const int nmt = (mg < 5) ? 2 : 1;         // tiles: mg and mg+8 (13 total)

    float* sQA  = (float*)(sm + OFF_QA);
    float* sRed = (float*)(sm + OFF_RED);
    float* sW1  = (float*)(sm + OFF_W1);

    // ---- prologue: fold W0 slices into registers ----
    const int h6 = tid & 63, eb = (tid >> 6) * 16;
    float rWk[16], rWd[16], rWq[16];
    #pragma unroll
    for (int i = 0; i < 16; i++) {
        int e = eb + i;
        float wa = __ldg(&W0[e * 64 + h6]);
        float wb = __ldg(&W0[(128 + e) * 64 + h6]);
        float wc = __ldg(&W0[(256 + e) * 64 + h6]);
        float wd = __ldg(&W0[(384 + e) * 64 + h6]);
        rWk[i] = wb - wc;
        rWd[i] = wd;
        rWq[i] = wa + wc;
    }
    for (int i = tid; i < 544; i += NTHR)
        ((uint32_t*)(sm + OFF_A + 200 * ROW_A))[i] = 0;   // zero A tail rows 200-207
    if (tid < 64) sW1[tid] = W1[tid];
    const float b1v = __ldg(b1);

    // kick both chunks of first batch
    issue_chunk(smb + OFF_STG,          keys, blockIdx.x, 0, tid);
    issue_chunk(smb + OFF_STG + STG_SZ, keys, blockIdx.x, 1, tid);
    __syncthreads();

    // ---- prologue: qA for this CTA's batches (fp32 exact) ----
    {
        int jj = 0;
        for (int b = blockIdx.x; b < B_SZ; b += GRID, jj++) {
            const float* qb = query + (size_t)b * E_DIM;
            float p = 0.f;
            #pragma unroll
            for (int i = 0; i < 16; i++)
                p += __ldg(&qb[eb + i]) * rWq[i];
            sRed[(tid >> 6) * 64 + h6] = p;
            __syncthreads();
            if (tid < 64) {
                float s = __ldg(&b0[tid]);
                #pragma unroll
                for (int g = 0; g < 8; g++) s += sRed[g * 64 + tid];
                sQA[jj * 64 + tid] = s;
            }
            __syncthreads();
        }
    }

    // epilogue per-thread W1 values (8 cols of this warp's n-half)
    float w1v[8];
    #pragma unroll
    for (int nt = 0; nt < 4; nt++) {
        w1v[2 * nt]     = sW1[ng * 32 + nt * 8 + 2 * lr];
        w1v[2 * nt + 1] = sW1[ng * 32 + nt * 8 + 2 * lr + 1];
    }

    // ldmatrix bases
    const uint32_t aB = smb + OFF_A  + (lane & 15) * ROW_A + (lane >> 4) * 16;
    const uint32_t bB = smb + OFF_BH + (ng * 32 + (lane & 7)) * ROW_B + ((lane >> 3) & 3) * 16;

    int j = 0;
    for (int b = blockIdx.x; b < B_SZ; b += GRID, j++) {
        const int nb = b + GRID;

        // ---- chunk 0 ready: convert rows 0-99, build W_b ----
        CP_WAIT(1);
        __syncthreads();                                   // (1)
        {
            const float4* s4 = (const float4*)(sm + OFF_STG);
            #pragma unroll
            for (int i = 0; i < 7; i++) {
                int idx = i * NTHR + tid;
                if (idx < 3200) {
                    float4 kv = s4[idx];
                    int row = idx >> 5, cc = idx & 31;
                    *(uint2*)(sm + OFF_A + row * ROW_A + cc * 8) =
                        make_uint2(pkf16(kv.x, kv.y), pkf16(kv.z, kv.w));
                }
            }
            // W_b = Wk + diag(q_b)·Wd, fp16 single-rounded
            const float* qb = query + (size_t)b * E_DIM;
            #pragma unroll
            for (int i = 0; i < 8; i++) {
                int e = eb + 2 * i;
                float v0 = fmaf(__ldg(&qb[e]),     rWd[2 * i],     rWk[2 * i]);
                float v1 = fmaf(__ldg(&qb[e + 1]), rWd[2 * i + 1], rWk[2 * i + 1]);
                *(uint32_t*)(sm + OFF_BH + h6 * ROW_B + e * 2) = pkf16(v0, v1);
            }
        }

        // ---- chunk 1 ready: refill buf0 (next batch), convert rows 100-199 ----
        CP_WAIT(0);
        __syncthreads();                                   // (2)
        if (nb < B_SZ) issue_chunk(smb + OFF_STG, keys, nb, 0, tid);
        {
            const float4* s4 = (const float4*)(sm + OFF_STG + STG_SZ);
            #pragma unroll
            for (int i = 0; i < 7; i++) {
                int idx = i * NTHR + tid;
                if (idx < 3200) {
                    float4 kv = s4[idx];
                    int row = 100 + (idx >> 5), cc = idx & 31;
                    *(uint2*)(sm + OFF_A + row * ROW_A + cc * 8) =
                        make_uint2(pkf16(kv.x, kv.y), pkf16(kv.z, kv.w));
                }
            }
        }
        __syncthreads();                                   // (3) A + B complete
        if (nb < B_SZ) issue_chunk(smb + OFF_STG + STG_SZ, keys, nb, 1, tid);

        // ---- mma: warp (mg, ng) -> tiles {mg, mg+8}, n-cols [ng*32, ng*32+32) ----
        float acc[2][4][4];
        #pragma unroll
        for (int mt = 0; mt < 2; mt++)
            #pragma unroll
            for (int nt = 0; nt < 4; nt++)
                #pragma unroll
                for (int t = 0; t < 4; t++) acc[mt][nt][t] = 0.f;

        #pragma unroll
        for (int kh = 0; kh < 2; kh++) {
            uint32_t bf[4][4][2];                          // [nt][klocal][2]
            #pragma unroll
            for (int nt = 0; nt < 4; nt++)
                #pragma unroll
                for (int k2 = 0; k2 < 2; k2++) {
                    uint32_t t[4];
                    LDSM4(t, bB + nt * (8 * ROW_B) + (2 * kh + k2) * 64);
                    bf[nt][2 * k2][0] = t[0];     bf[nt][2 * k2][1] = t[1];
                    bf[nt][2 * k2 + 1][0] = t[2]; bf[nt][2 * k2 + 1][1] = t[3];
                }
            #pragma unroll
            for (int mt = 0; mt < 2; mt++) {
                if (mt < nmt) {
                    int gmt = mg + mt * 8;
                    #pragma unroll
                    for (int kl = 0; kl < 4; kl++) {
                        uint32_t a[4];
                        LDSM4(a, aB + gmt * (16 * ROW_A) + (kh * 4 + kl) * 32);
                        #pragma unroll
                        for (int nt = 0; nt < 4; nt++)
                            mma_f16(acc[mt][nt], a, bf[nt][kl][0], bf[nt][kl][1]);
                    }
                }
            }
        }

        // ---- epilogue: h = relu(acc + qA), partial dot, plain STS (no atomics) ----
        const float* qaj = sQA + j * 64 + ng * 32;
        #pragma unroll
        for (int mt = 0; mt < 2; mt++) {
            if (mt < nmt) {
                int gmt = mg + mt * 8;
                float p0 = 0.f, p1 = 0.f;
                #pragma unroll
                for (int nt = 0; nt < 4; nt++) {
                    int c = nt * 8 + 2 * lr;
                    p0 += fmaxf(acc[mt][nt][0] + qaj[c],     0.f) * w1v[2 * nt]
                        + fmaxf(acc[mt][nt][1] + qaj[c + 1], 0.f) * w1v[2 * nt + 1];
                    p1 += fmaxf(acc[mt][nt][2] + qaj[c],     0.f) * w1v[2 * nt]
                        + fmaxf(acc[mt][nt][3] + qaj[c + 1], 0.f) * w1v[2 * nt + 1];
                }
                p0 += __shfl_xor_sync(0xffffffffu, p0, 1);
                p0 += __shfl_xor_sync(0xffffffffu, p0, 2);
                p1 += __shfl_xor_sync(0xffffffffu, p1, 1);
                p1 += __shfl_xor_sync(0xffffffffu, p1, 2);
                if (lr == 0) {
                    sRed[ng * 208 + gmt * 16 + lq]     = p0;
                    sRed[ng * 208 + gmt * 16 + lq + 8] = p1;
                }
            }
        }
        __syncthreads();                                   // (4)
        if (tid < T_SZ)
            out[(size_t)b * T_SZ + tid] = sRed[tid] + sRed[208 + tid] + b1v;
        // next iteration's CP_WAIT+sync orders A/B/sRed reuse
    }
}

extern "C" void kernel_launch(void* const* d_in, const int* in_sizes, int n_in,
                              void* d_out, int out_size) {
    const float* query = (const float*)d_in[0];
    const float* keys  = (const float*)d_in[1];
    const float* W0    = (const float*)d_in[2];
    const float* b0    = (const float*)d_in[3];
    const float* W1    = (const float*)d_in[4];
    const float* b1    = (const float*)d_in[5];
    float* out = (float*)d_out;

    cudaFuncSetAttribute(lau_main, cudaFuncAttributeMaxDynamicSharedMemorySize, SMEM_BYTES);
    lau_main<<<GRID, NTHR, SMEM_BYTES>>>(keys, query, W0, b0, W1, b1, out);
}